// round 3
// baseline (speedup 1.0000x reference)
#include <cuda_runtime.h>
#include <math.h>
#include <stdint.h>

#define BSZ 8192

// ---------------- scratch (static device globals; no allocs allowed) -------
__device__ float g_v[BSZ * 288];      // conv front output
__device__ float g_cat[BSZ * 384];    // [emb(256) | comm(128)]
__device__ float g_h[BSZ * 512];      // residual stream
__device__ float g_u[BSZ * 512];      // rmsnorm output
__device__ float g_xz[BSZ * 2048];    // in_proj output (silu(conv(x)) | z)
__device__ float g_xdbl[BSZ * 64];    // x_proj output (dt_rank 32 | B 16 | C 16)
__device__ float g_dt[BSZ * 1024];    // softplus(dt)
__device__ float g_y[BSZ * 1024];     // gated y before out_proj

// ---------------- front conv: obs (B,3,5,5) -> relu conv3x3 -> (B,288) ----
__global__ void conv_front(const float* __restrict__ obs,
                           const float* __restrict__ cw,
                           const float* __restrict__ cb) {
    int i = blockIdx.x * blockDim.x + threadIdx.x;
    if (i >= BSZ * 288) return;
    int b = i / 288, r = i % 288;
    int oc = r / 9, oi = (r % 9) / 3, oj = r % 3;
    const float* o = obs + b * 75;
    float s = cb[oc];
#pragma unroll
    for (int ci = 0; ci < 3; ci++)
#pragma unroll
        for (int ki = 0; ki < 3; ki++)
#pragma unroll
            for (int kj = 0; kj < 3; kj++)
                s += o[ci * 25 + (oi + ki) * 5 + (oj + kj)] *
                     cw[((oc * 3 + ci) * 3 + ki) * 3 + kj];
    g_v[i] = fmaxf(s, 0.f);
}

__global__ void copy_comm(const float* __restrict__ c) {
    int i = blockIdx.x * blockDim.x + threadIdx.x;
    if (i >= BSZ * 128) return;
    int b = i >> 7, j = i & 127;
    g_cat[b * 384 + 256 + j] = c[i];
}

// ---------------- SGEMM: C[M,N] (+)= act(A[M,K] @ B[K,N] + bias) ----------
// BM=128, BN=64, BK=16, 256 threads, 8x4 per-thread tile.
// ACT: 0=none 1=relu 2=tanh 3=softplus 4=convsilu-on-x-half (cols<1024)
// Requires: M%128==0, N%64==0, K%16==0 (all shapes here comply)
template <int ACT, bool ACCUM, bool BIAS>
__global__ __launch_bounds__(256) void sgemm(
    const float* __restrict__ A, int lda,
    const float* __restrict__ B, int ldb,
    const float* __restrict__ bias,
    float* __restrict__ C, int ldc,
    int M, int N, int K,
    const float* __restrict__ cw1d, const float* __restrict__ cb1d) {
    __shared__ float As[16][128];
    __shared__ float Bs[16][64];
    int tid  = threadIdx.x;
    int brow = blockIdx.y * 128;
    int bcol = blockIdx.x * 64;
    int tm = (tid >> 4) * 8;
    int tn = (tid & 15) * 4;
    float acc[8][4] = {};

    for (int kt = 0; kt < K; kt += 16) {
#pragma unroll
        for (int i = 0; i < 2; i++) {
            int idx = tid + i * 256;
            int r = idx >> 2, kq = (idx & 3) << 2;
            float4 a = *(const float4*)(A + (size_t)(brow + r) * lda + kt + kq);
            As[kq + 0][r] = a.x; As[kq + 1][r] = a.y;
            As[kq + 2][r] = a.z; As[kq + 3][r] = a.w;
        }
        {
            int r = tid >> 4, nq = (tid & 15) << 2;
            float4 bv = *(const float4*)(B + (size_t)(kt + r) * ldb + bcol + nq);
            *(float4*)&Bs[r][nq] = bv;
        }
        __syncthreads();
#pragma unroll
        for (int k = 0; k < 16; k++) {
            float ar[8], br[4];
            *(float4*)(ar)     = *(const float4*)&As[k][tm];
            *(float4*)(ar + 4) = *(const float4*)&As[k][tm + 4];
            *(float4*)(br)     = *(const float4*)&Bs[k][tn];
#pragma unroll
            for (int i = 0; i < 8; i++)
#pragma unroll
                for (int j = 0; j < 4; j++)
                    acc[i][j] = fmaf(ar[i], br[j], acc[i][j]);
        }
        __syncthreads();
    }

    float bv[4] = {0.f, 0.f, 0.f, 0.f};
    if (BIAS) *(float4*)bv = *(const float4*)(bias + bcol + tn);
    // convsilu epilogue params (ACT==4): applied only to columns < 1024
    float cwv[4], cbv[4];
    bool xhalf = false;
    if (ACT == 4) {
        xhalf = (bcol + tn) < 1024;   // 64-col tiles never straddle the 1024 boundary
        if (xhalf) {
#pragma unroll
            for (int j = 0; j < 4; j++) {
                int col = bcol + tn + j;
                cwv[j] = cw1d[col * 4 + 3];
                cbv[j] = cb1d[col];
            }
        }
    }
#pragma unroll
    for (int i = 0; i < 8; i++) {
        float* crow = C + (size_t)(brow + tm + i) * ldc + bcol + tn;
        float4 prev = make_float4(0.f, 0.f, 0.f, 0.f);
        if (ACCUM) prev = *(const float4*)crow;
        float r[4];
#pragma unroll
        for (int j = 0; j < 4; j++) {
            float v = acc[i][j];
            if (BIAS) v += bv[j];
            if (ACT == 1) v = fmaxf(v, 0.f);
            else if (ACT == 2) v = tanhf(v);
            else if (ACT == 3) v = (v > 20.f) ? v : log1pf(expf(v));
            else if (ACT == 4) {
                if (xhalf) {
                    v = v * cwv[j] + cbv[j];
                    v = v / (1.f + expf(-v));
                }
            }
            r[j] = v;
        }
        if (ACCUM) { r[0] += prev.x; r[1] += prev.y; r[2] += prev.z; r[3] += prev.w; }
        *(float4*)crow = make_float4(r[0], r[1], r[2], r[3]);
    }
}

// ---------------- rmsnorm: one warp per 512-row -----------------------------
__global__ void rmsnorm_k(const float* __restrict__ x, const float* __restrict__ w,
                          float* __restrict__ out) {
    int warp = (blockIdx.x * blockDim.x + threadIdx.x) >> 5;
    int lane = threadIdx.x & 31;
    if (warp >= BSZ) return;
    const float4* xr = (const float4*)(x + (size_t)warp * 512);
    float4 v[4];
    float ss = 0.f;
#pragma unroll
    for (int i = 0; i < 4; i++) {
        v[i] = xr[lane + i * 32];
        ss += v[i].x * v[i].x + v[i].y * v[i].y + v[i].z * v[i].z + v[i].w * v[i].w;
    }
#pragma unroll
    for (int o = 16; o > 0; o >>= 1) ss += __shfl_xor_sync(0xffffffffu, ss, o);
    float sc = rsqrtf(ss * (1.f / 512.f) + 1e-5f);
    float4* orow = (float4*)(out + (size_t)warp * 512);
    const float4* wr = (const float4*)w;
#pragma unroll
    for (int i = 0; i < 4; i++) {
        float4 wv = wr[lane + i * 32];
        float4 r;
        r.x = v[i].x * sc * wv.x; r.y = v[i].y * sc * wv.y;
        r.z = v[i].z * sc * wv.z; r.w = v[i].w * sc * wv.w;
        orow[lane + i * 32] = r;
    }
}

// ---------------- fused y = (dt*<B,C> + D)*x*silu(z) ------------------------
__global__ void fused_y(const float* __restrict__ Dp) {
    int b = blockIdx.x;
    __shared__ float sh[16];
    __shared__ float bc_sh;
    int t = threadIdx.x;
    if (t < 16) sh[t] = g_xdbl[b * 64 + 32 + t] * g_xdbl[b * 64 + 48 + t];
    __syncthreads();
    if (t == 0) {
        float s = 0.f;
#pragma unroll
        for (int i = 0; i < 16; i++) s += sh[i];
        bc_sh = s;
    }
    __syncthreads();
    float bc = bc_sh;
    for (int d = t; d < 1024; d += 256) {
        float x  = g_xz[(size_t)b * 2048 + d];
        float z  = g_xz[(size_t)b * 2048 + 1024 + d];
        float dt = g_dt[(size_t)b * 1024 + d];
        float y  = (dt * bc + Dp[d]) * x;
        float sz = z / (1.f + expf(-z));
        g_y[(size_t)b * 1024 + d] = y * sz;
    }
}

// ---------------- action + value heads: one warp per row --------------------
__global__ void heads_k(const float* __restrict__ aw, const float* __restrict__ ab,
                        const float* __restrict__ vw, const float* __restrict__ vb,
                        float* __restrict__ out) {
    int warp = (blockIdx.x * blockDim.x + threadIdx.x) >> 5;
    int lane = threadIdx.x & 31;
    if (warp >= BSZ) return;
    const float* u = g_u + (size_t)warp * 512;
    float s0 = 0, s1 = 0, s2 = 0, s3 = 0, s4 = 0;
    for (int d = lane; d < 512; d += 32) {
        float uv = u[d];
        float4 w4 = *(const float4*)(aw + d * 4);
        s0 += uv * w4.x; s1 += uv * w4.y; s2 += uv * w4.z; s3 += uv * w4.w;
        s4 += uv * vw[d];
    }
#pragma unroll
    for (int o = 16; o > 0; o >>= 1) {
        s0 += __shfl_xor_sync(0xffffffffu, s0, o);
        s1 += __shfl_xor_sync(0xffffffffu, s1, o);
        s2 += __shfl_xor_sync(0xffffffffu, s2, o);
        s3 += __shfl_xor_sync(0xffffffffu, s3, o);
        s4 += __shfl_xor_sync(0xffffffffu, s4, o);
    }
    if (lane == 0) {
        out[warp * 4 + 0] = s0 + ab[0];
        out[warp * 4 + 1] = s1 + ab[1];
        out[warp * 4 + 2] = s2 + ab[2];
        out[warp * 4 + 3] = s3 + ab[3];
        out[(size_t)BSZ * 4 + (size_t)BSZ * 128 + warp] = s4 + vb[0];
    }
}

// ---------------- launch --------------------------------------------------
extern "C" void kernel_launch(void* const* d_in, const int* in_sizes, int n_in,
                              void* d_out, int out_size) {
    const float* obs     = (const float*)d_in[0];
    const float* comm_in = (const float*)d_in[1];
    const float* conv_w  = (const float*)d_in[2];
    const float* conv_b  = (const float*)d_in[3];
    const float* enc_w   = (const float*)d_in[4];
    const float* enc_b   = (const float*)d_in[5];
    const float* proj_w  = (const float*)d_in[6];
    const float* proj_b  = (const float*)d_in[7];
    const float* norm_w  = (const float*)d_in[8];
    const float* in_proj_w = (const float*)d_in[9];
    const float* conv1d_w  = (const float*)d_in[10];
    const float* conv1d_b  = (const float*)d_in[11];
    const float* x_proj_w  = (const float*)d_in[12];
    const float* dt_proj_w = (const float*)d_in[13];
    const float* dt_proj_b = (const float*)d_in[14];
    // d_in[15] = A_log: dead (h0 == 0 makes dA irrelevant at L=1)
    const float* D_param    = (const float*)d_in[16];
    const float* out_proj_w = (const float*)d_in[17];
    const float* final_norm = (const float*)d_in[18];
    const float* act_w  = (const float*)d_in[19];
    const float* act_b  = (const float*)d_in[20];
    const float* comm_w = (const float*)d_in[21];
    const float* comm_b = (const float*)d_in[22];
    const float* val_w  = (const float*)d_in[23];
    const float* val_b  = (const float*)d_in[24];
    float* out = (float*)d_out;

    float* gv    = nullptr; cudaGetSymbolAddress((void**)&gv, g_v);
    float* gcat  = nullptr; cudaGetSymbolAddress((void**)&gcat, g_cat);
    float* gh    = nullptr; cudaGetSymbolAddress((void**)&gh, g_h);
    float* gu    = nullptr; cudaGetSymbolAddress((void**)&gu, g_u);
    float* gxz   = nullptr; cudaGetSymbolAddress((void**)&gxz, g_xz);
    float* gxdbl = nullptr; cudaGetSymbolAddress((void**)&gxdbl, g_xdbl);
    float* gdt   = nullptr; cudaGetSymbolAddress((void**)&gdt, g_dt);
    float* gy    = nullptr; cudaGetSymbolAddress((void**)&gy, g_y);

    const int M = BSZ;

    // front
    conv_front<<<(BSZ * 288 + 255) / 256, 256>>>(obs, conv_w, conv_b);
    sgemm<1, false, true><<<dim3(256 / 64, M / 128), 256>>>(
        gv, 288, enc_w, 256, enc_b, gcat, 384, M, 256, 288, nullptr, nullptr);
    copy_comm<<<(BSZ * 128 + 255) / 256, 256>>>(comm_in);
    sgemm<1, false, true><<<dim3(512 / 64, M / 128), 256>>>(
        gcat, 384, proj_w, 512, proj_b, gh, 512, M, 512, 384, nullptr, nullptr);

    // two mamba layers (L=1 closed form)
    for (int l = 0; l < 2; l++) {
        rmsnorm_k<<<BSZ / 8, 256>>>(gh, norm_w + l * 512, gu);
        // in_proj with fused depthwise-conv-tap + silu on x-half columns
        sgemm<4, false, false><<<dim3(2048 / 64, M / 128), 256>>>(
            gu, 512, in_proj_w + (size_t)l * 512 * 2048, 2048, nullptr,
            gxz, 2048, M, 2048, 512,
            conv1d_w + (size_t)l * 1024 * 4, conv1d_b + (size_t)l * 1024);
        sgemm<0, false, false><<<dim3(64 / 64, M / 128), 256>>>(
            gxz, 2048, x_proj_w + (size_t)l * 1024 * 64, 64, nullptr,
            gxdbl, 64, M, 64, 1024, nullptr, nullptr);
        sgemm<3, false, true><<<dim3(1024 / 64, M / 128), 256>>>(
            gxdbl, 64, dt_proj_w + (size_t)l * 32 * 1024, 1024,
            dt_proj_b + (size_t)l * 1024, gdt, 1024, M, 1024, 32, nullptr, nullptr);
        fused_y<<<BSZ, 256>>>(D_param + (size_t)l * 1024);
        sgemm<0, true, false><<<dim3(512 / 64, M / 128), 256>>>(
            gy, 1024, out_proj_w + (size_t)l * 1024 * 512, 512, nullptr,
            gh, 512, M, 512, 1024, nullptr, nullptr);
    }

    // final norm + heads
    rmsnorm_k<<<BSZ / 8, 256>>>(gh, final_norm, gu);
    sgemm<2, false, true><<<dim3(128 / 64, M / 128), 256>>>(
        gu, 512, comm_w, 128, comm_b, out + (size_t)BSZ * 4, 128, M, 128, 512,
        nullptr, nullptr);
    heads_k<<<BSZ / 8, 256>>>(act_w, act_b, val_w, val_b, out);
}

// round 4
// speedup vs baseline: 1.4795x; 1.4795x over previous
#include <cuda_runtime.h>
#include <math.h>
#include <stdint.h>

#define BSZ 8192

// ---------------- scratch (static device globals; no allocs allowed) -------
__device__ float g_v[BSZ * 288];      // conv front output
__device__ float g_cat[BSZ * 384];    // [emb(256) | comm(128)]
__device__ float g_h[BSZ * 512];      // residual stream
__device__ float g_u[BSZ * 512];      // rmsnorm output
__device__ float g_xz[BSZ * 2048];    // in_proj output (silu(conv(x)) | z)
__device__ float g_xdbl[BSZ * 64];    // x_proj output (dt 32 | B 16 | C 16)
__device__ float g_dt[BSZ * 1024];    // softplus(dt)
__device__ float g_y[BSZ * 1024];     // gated y before out_proj

// ---------------- helpers ---------------------------------------------------
__device__ __forceinline__ uint32_t f2tf32(float f) {
    uint32_t u;
    asm("cvt.rna.tf32.f32 %0, %1;" : "=r"(u) : "f"(f));
    return u;
}

__device__ __forceinline__ void mma_tf32(float* d, const uint32_t* a,
                                         const uint32_t* b, const float* c) {
    asm volatile(
        "mma.sync.aligned.m16n8k8.row.col.f32.tf32.tf32.f32 "
        "{%0,%1,%2,%3}, {%4,%5,%6,%7}, {%8,%9}, {%10,%11,%12,%13};"
        : "=f"(d[0]), "=f"(d[1]), "=f"(d[2]), "=f"(d[3])
        : "r"(a[0]), "r"(a[1]), "r"(a[2]), "r"(a[3]),
          "r"(b[0]), "r"(b[1]),
          "f"(c[0]), "f"(c[1]), "f"(c[2]), "f"(c[3]));
}

// ---------------- front conv: obs (B,3,5,5) -> relu conv3x3 -> (B,288) ----
__global__ void conv_front(const float* __restrict__ obs,
                           const float* __restrict__ cw,
                           const float* __restrict__ cb) {
    int i = blockIdx.x * blockDim.x + threadIdx.x;
    if (i >= BSZ * 288) return;
    int b = i / 288, r = i % 288;
    int oc = r / 9, oi = (r % 9) / 3, oj = r % 3;
    const float* o = obs + b * 75;
    float s = cb[oc];
#pragma unroll
    for (int ci = 0; ci < 3; ci++)
#pragma unroll
        for (int ki = 0; ki < 3; ki++)
#pragma unroll
            for (int kj = 0; kj < 3; kj++)
                s += o[ci * 25 + (oi + ki) * 5 + (oj + kj)] *
                     cw[((oc * 3 + ci) * 3 + ki) * 3 + kj];
    g_v[i] = fmaxf(s, 0.f);
}

__global__ void copy_comm(const float* __restrict__ c) {
    int i = blockIdx.x * blockDim.x + threadIdx.x;
    if (i >= BSZ * 128) return;
    int b = i >> 7, j = i & 127;
    g_cat[b * 384 + 256 + j] = c[i];
}

// ---------------- TF32 tensor-core GEMM -------------------------------------
// C[M,N] (+)= act(A[M,K] @ B[K,N] + bias)
// BM=128, BN=64, BK=32, 256 threads (8 warps, 4x2 warp grid, 32x32 per warp).
// ACT: 0=none 1=relu 2=tanh 3=softplus 4=convsilu-on-x-half (cols<1024)
// Requires: M%128==0, N%64==0, K%32==0 (all shapes here comply)
template <int ACT, bool ACCUM, bool BIAS>
__global__ __launch_bounds__(256) void tgemm(
    const float* __restrict__ A, int lda,
    const float* __restrict__ B, int ldb,
    const float* __restrict__ bias,
    float* __restrict__ C, int ldc,
    int M, int N, int K,
    const float* __restrict__ cw1d, const float* __restrict__ cb1d) {
    __shared__ uint32_t As[32][136];  // [k][m], pad 8 -> conflict-free frag loads
    __shared__ uint32_t Bs[32][72];   // [k][n], pad 8

    int tid  = threadIdx.x;
    int lane = tid & 31;
    int warp = tid >> 5;
    int g  = lane >> 2;      // group id 0..7
    int tg = lane & 3;       // thread in group
    int wm = (warp & 3) * 32;
    int wn = (warp >> 2) * 32;
    int brow = blockIdx.y * 128;
    int bcol = blockIdx.x * 64;

    float acc[2][4][4];
#pragma unroll
    for (int mt = 0; mt < 2; mt++)
#pragma unroll
        for (int nt = 0; nt < 4; nt++)
#pragma unroll
            for (int q = 0; q < 4; q++) acc[mt][nt][q] = 0.f;

    for (int kt = 0; kt < K; kt += 32) {
        // load A tile 128x32 (transposed store, tf32 convert)
#pragma unroll
        for (int i = 0; i < 4; i++) {
            int idx = tid + i * 256;
            int r = idx >> 3, kq = (idx & 7) << 2;
            float4 a = *(const float4*)(A + (size_t)(brow + r) * lda + kt + kq);
            As[kq + 0][r] = f2tf32(a.x);
            As[kq + 1][r] = f2tf32(a.y);
            As[kq + 2][r] = f2tf32(a.z);
            As[kq + 3][r] = f2tf32(a.w);
        }
        // load B tile 32x64
#pragma unroll
        for (int i = 0; i < 2; i++) {
            int idx = tid + i * 256;
            int kr = idx >> 4, nq = (idx & 15) << 2;
            float4 b = *(const float4*)(B + (size_t)(kt + kr) * ldb + bcol + nq);
            uint32_t* p = &Bs[kr][nq];
            p[0] = f2tf32(b.x); p[1] = f2tf32(b.y);
            p[2] = f2tf32(b.z); p[3] = f2tf32(b.w);
        }
        __syncthreads();
#pragma unroll
        for (int ks = 0; ks < 4; ks++) {
            int k0 = ks * 8;
            uint32_t af[2][4], bf[4][2];
#pragma unroll
            for (int mt = 0; mt < 2; mt++) {
                int mb = wm + mt * 16 + g;
                af[mt][0] = As[k0 + tg][mb];
                af[mt][1] = As[k0 + tg][mb + 8];
                af[mt][2] = As[k0 + tg + 4][mb];
                af[mt][3] = As[k0 + tg + 4][mb + 8];
            }
#pragma unroll
            for (int nt = 0; nt < 4; nt++) {
                int nb = wn + nt * 8 + g;
                bf[nt][0] = Bs[k0 + tg][nb];
                bf[nt][1] = Bs[k0 + tg + 4][nb];
            }
#pragma unroll
            for (int mt = 0; mt < 2; mt++)
#pragma unroll
                for (int nt = 0; nt < 4; nt++)
                    mma_tf32(acc[mt][nt], af[mt], bf[nt], acc[mt][nt]);
        }
        __syncthreads();
    }

    // epilogue
#pragma unroll
    for (int nt = 0; nt < 4; nt++) {
        int col = bcol + wn + nt * 8 + 2 * tg;   // two consecutive cols
        float bv0 = 0.f, bv1 = 0.f;
        if (BIAS) { bv0 = bias[col]; bv1 = bias[col + 1]; }
        float cw0 = 0.f, cw1 = 0.f, cb0 = 0.f, cb1 = 0.f;
        bool xhalf = false;
        if (ACT == 4) {
            xhalf = col < 1024;  // 64-wide tiles never straddle 1024
            if (xhalf) {
                cw0 = cw1d[col * 4 + 3]; cw1 = cw1d[(col + 1) * 4 + 3];
                cb0 = cb1d[col];         cb1 = cb1d[col + 1];
            }
        }
#pragma unroll
        for (int mt = 0; mt < 2; mt++) {
#pragma unroll
            for (int half = 0; half < 2; half++) {
                int row = brow + wm + mt * 16 + g + half * 8;
                float v0 = acc[mt][nt][half * 2 + 0];
                float v1 = acc[mt][nt][half * 2 + 1];
                if (BIAS) { v0 += bv0; v1 += bv1; }
                if (ACT == 1) { v0 = fmaxf(v0, 0.f); v1 = fmaxf(v1, 0.f); }
                else if (ACT == 2) { v0 = tanhf(v0); v1 = tanhf(v1); }
                else if (ACT == 3) {
                    v0 = (v0 > 20.f) ? v0 : log1pf(expf(v0));
                    v1 = (v1 > 20.f) ? v1 : log1pf(expf(v1));
                } else if (ACT == 4) {
                    if (xhalf) {
                        v0 = v0 * cw0 + cb0; v0 = v0 / (1.f + expf(-v0));
                        v1 = v1 * cw1 + cb1; v1 = v1 / (1.f + expf(-v1));
                    }
                }
                float* cp = C + (size_t)row * ldc + col;
                if (ACCUM) {
                    float2 prev = *(const float2*)cp;
                    v0 += prev.x; v1 += prev.y;
                }
                *(float2*)cp = make_float2(v0, v1);
            }
        }
    }
}

// ---------------- rmsnorm: one warp per 512-row -----------------------------
__global__ void rmsnorm_k(const float* __restrict__ x, const float* __restrict__ w,
                          float* __restrict__ out) {
    int warp = (blockIdx.x * blockDim.x + threadIdx.x) >> 5;
    int lane = threadIdx.x & 31;
    if (warp >= BSZ) return;
    const float4* xr = (const float4*)(x + (size_t)warp * 512);
    float4 v[4];
    float ss = 0.f;
#pragma unroll
    for (int i = 0; i < 4; i++) {
        v[i] = xr[lane + i * 32];
        ss += v[i].x * v[i].x + v[i].y * v[i].y + v[i].z * v[i].z + v[i].w * v[i].w;
    }
#pragma unroll
    for (int o = 16; o > 0; o >>= 1) ss += __shfl_xor_sync(0xffffffffu, ss, o);
    float sc = rsqrtf(ss * (1.f / 512.f) + 1e-5f);
    float4* orow = (float4*)(out + (size_t)warp * 512);
    const float4* wr = (const float4*)w;
#pragma unroll
    for (int i = 0; i < 4; i++) {
        float4 wv = wr[lane + i * 32];
        float4 r;
        r.x = v[i].x * sc * wv.x; r.y = v[i].y * sc * wv.y;
        r.z = v[i].z * sc * wv.z; r.w = v[i].w * sc * wv.w;
        orow[lane + i * 32] = r;
    }
}

// ---------------- fused y = (dt*<B,C> + D)*x*silu(z) ------------------------
__global__ void fused_y(const float* __restrict__ Dp) {
    int b = blockIdx.x;
    __shared__ float sh[16];
    __shared__ float bc_sh;
    int t = threadIdx.x;
    if (t < 16) sh[t] = g_xdbl[b * 64 + 32 + t] * g_xdbl[b * 64 + 48 + t];
    __syncthreads();
    if (t == 0) {
        float s = 0.f;
#pragma unroll
        for (int i = 0; i < 16; i++) s += sh[i];
        bc_sh = s;
    }
    __syncthreads();
    float bc = bc_sh;
    for (int d = t; d < 1024; d += 256) {
        float x  = g_xz[(size_t)b * 2048 + d];
        float z  = g_xz[(size_t)b * 2048 + 1024 + d];
        float dt = g_dt[(size_t)b * 1024 + d];
        float y  = (dt * bc + Dp[d]) * x;
        float sz = z / (1.f + expf(-z));
        g_y[(size_t)b * 1024 + d] = y * sz;
    }
}

// ---------------- action + value heads: one warp per row --------------------
__global__ void heads_k(const float* __restrict__ aw, const float* __restrict__ ab,
                        const float* __restrict__ vw, const float* __restrict__ vb,
                        float* __restrict__ out) {
    int warp = (blockIdx.x * blockDim.x + threadIdx.x) >> 5;
    int lane = threadIdx.x & 31;
    if (warp >= BSZ) return;
    const float* u = g_u + (size_t)warp * 512;
    float s0 = 0, s1 = 0, s2 = 0, s3 = 0, s4 = 0;
    for (int d = lane; d < 512; d += 32) {
        float uv = u[d];
        float4 w4 = *(const float4*)(aw + d * 4);
        s0 += uv * w4.x; s1 += uv * w4.y; s2 += uv * w4.z; s3 += uv * w4.w;
        s4 += uv * vw[d];
    }
#pragma unroll
    for (int o = 16; o > 0; o >>= 1) {
        s0 += __shfl_xor_sync(0xffffffffu, s0, o);
        s1 += __shfl_xor_sync(0xffffffffu, s1, o);
        s2 += __shfl_xor_sync(0xffffffffu, s2, o);
        s3 += __shfl_xor_sync(0xffffffffu, s3, o);
        s4 += __shfl_xor_sync(0xffffffffu, s4, o);
    }
    if (lane == 0) {
        out[warp * 4 + 0] = s0 + ab[0];
        out[warp * 4 + 1] = s1 + ab[1];
        out[warp * 4 + 2] = s2 + ab[2];
        out[warp * 4 + 3] = s3 + ab[3];
        out[(size_t)BSZ * 4 + (size_t)BSZ * 128 + warp] = s4 + vb[0];
    }
}

// ---------------- launch --------------------------------------------------
extern "C" void kernel_launch(void* const* d_in, const int* in_sizes, int n_in,
                              void* d_out, int out_size) {
    const float* obs     = (const float*)d_in[0];
    const float* comm_in = (const float*)d_in[1];
    const float* conv_w  = (const float*)d_in[2];
    const float* conv_b  = (const float*)d_in[3];
    const float* enc_w   = (const float*)d_in[4];
    const float* enc_b   = (const float*)d_in[5];
    const float* proj_w  = (const float*)d_in[6];
    const float* proj_b  = (const float*)d_in[7];
    const float* norm_w  = (const float*)d_in[8];
    const float* in_proj_w = (const float*)d_in[9];
    const float* conv1d_w  = (const float*)d_in[10];
    const float* conv1d_b  = (const float*)d_in[11];
    const float* x_proj_w  = (const float*)d_in[12];
    const float* dt_proj_w = (const float*)d_in[13];
    const float* dt_proj_b = (const float*)d_in[14];
    // d_in[15] = A_log: dead (h0 == 0 makes dA irrelevant at L=1)
    const float* D_param    = (const float*)d_in[16];
    const float* out_proj_w = (const float*)d_in[17];
    const float* final_norm = (const float*)d_in[18];
    const float* act_w  = (const float*)d_in[19];
    const float* act_b  = (const float*)d_in[20];
    const float* comm_w = (const float*)d_in[21];
    const float* comm_b = (const float*)d_in[22];
    const float* val_w  = (const float*)d_in[23];
    const float* val_b  = (const float*)d_in[24];
    float* out = (float*)d_out;

    float* gv    = nullptr; cudaGetSymbolAddress((void**)&gv, g_v);
    float* gcat  = nullptr; cudaGetSymbolAddress((void**)&gcat, g_cat);
    float* gh    = nullptr; cudaGetSymbolAddress((void**)&gh, g_h);
    float* gu    = nullptr; cudaGetSymbolAddress((void**)&gu, g_u);
    float* gxz   = nullptr; cudaGetSymbolAddress((void**)&gxz, g_xz);
    float* gxdbl = nullptr; cudaGetSymbolAddress((void**)&gxdbl, g_xdbl);
    float* gdt   = nullptr; cudaGetSymbolAddress((void**)&gdt, g_dt);
    float* gy    = nullptr; cudaGetSymbolAddress((void**)&gy, g_y);

    const int M = BSZ;

    // front
    conv_front<<<(BSZ * 288 + 255) / 256, 256>>>(obs, conv_w, conv_b);
    tgemm<1, false, true><<<dim3(256 / 64, M / 128), 256>>>(
        gv, 288, enc_w, 256, enc_b, gcat, 384, M, 256, 288, nullptr, nullptr);
    copy_comm<<<(BSZ * 128 + 255) / 256, 256>>>(comm_in);
    tgemm<1, false, true><<<dim3(512 / 64, M / 128), 256>>>(
        gcat, 384, proj_w, 512, proj_b, gh, 512, M, 512, 384, nullptr, nullptr);

    // two mamba layers (L=1 closed form)
    for (int l = 0; l < 2; l++) {
        rmsnorm_k<<<BSZ / 8, 256>>>(gh, norm_w + l * 512, gu);
        // in_proj with fused depthwise-conv-tap + silu on x-half columns
        tgemm<4, false, false><<<dim3(2048 / 64, M / 128), 256>>>(
            gu, 512, in_proj_w + (size_t)l * 512 * 2048, 2048, nullptr,
            gxz, 2048, M, 2048, 512,
            conv1d_w + (size_t)l * 1024 * 4, conv1d_b + (size_t)l * 1024);
        tgemm<0, false, false><<<dim3(64 / 64, M / 128), 256>>>(
            gxz, 2048, x_proj_w + (size_t)l * 1024 * 64, 64, nullptr,
            gxdbl, 64, M, 64, 1024, nullptr, nullptr);
        tgemm<3, false, true><<<dim3(1024 / 64, M / 128), 256>>>(
            gxdbl, 64, dt_proj_w + (size_t)l * 32 * 1024, 1024,
            dt_proj_b + (size_t)l * 1024, gdt, 1024, M, 1024, 32, nullptr, nullptr);
        fused_y<<<BSZ, 256>>>(D_param + (size_t)l * 1024);
        tgemm<0, true, false><<<dim3(512 / 64, M / 128), 256>>>(
            gy, 1024, out_proj_w + (size_t)l * 1024 * 512, 512, nullptr,
            gh, 512, M, 512, 1024, nullptr, nullptr);
    }

    // final norm + heads
    rmsnorm_k<<<BSZ / 8, 256>>>(gh, final_norm, gu);
    tgemm<2, false, true><<<dim3(128 / 64, M / 128), 256>>>(
        gu, 512, comm_w, 128, comm_b, out + (size_t)BSZ * 4, 128, M, 128, 512,
        nullptr, nullptr);
    heads_k<<<BSZ / 8, 256>>>(act_w, act_b, val_w, val_b, out);
}

// round 10
// speedup vs baseline: 2.5748x; 1.7403x over previous
#include <cuda_runtime.h>
#include <math.h>
#include <stdint.h>

#define BSZ 8192

// ---------------- scratch (static device globals; no allocs allowed) -------
__device__ float g_v[BSZ * 288];      // conv front output
__device__ float g_cat[BSZ * 384];    // [emb(256) | comm(128)]
__device__ float g_h[BSZ * 512];      // residual stream
__device__ float g_u[BSZ * 512];      // rmsnorm output
__device__ float g_xz[BSZ * 2048];    // in_proj output (silu(conv(x)) | z)
__device__ float g_xdbl[BSZ * 64];    // x_proj output (dt 32 | B 16 | C 16)
__device__ float g_dt[BSZ * 1024];    // softplus(dt)
__device__ float g_y[BSZ * 1024];     // gated y before out_proj

// ---------------- helpers ---------------------------------------------------
__device__ __forceinline__ uint32_t f2tf32(float f) {
    uint32_t u;
    asm("cvt.rna.tf32.f32 %0, %1;" : "=r"(u) : "f"(f));
    return u;
}

__device__ __forceinline__ void mma_tf32(float* d, const uint32_t* a,
                                         const uint32_t* b, const float* c) {
    asm volatile(
        "mma.sync.aligned.m16n8k8.row.col.f32.tf32.tf32.f32 "
        "{%0,%1,%2,%3}, {%4,%5,%6,%7}, {%8,%9}, {%10,%11,%12,%13};"
        : "=f"(d[0]), "=f"(d[1]), "=f"(d[2]), "=f"(d[3])
        : "r"(a[0]), "r"(a[1]), "r"(a[2]), "r"(a[3]),
          "r"(b[0]), "r"(b[1]),
          "f"(c[0]), "f"(c[1]), "f"(c[2]), "f"(c[3]));
}

__device__ __forceinline__ void cp16(float* smem_dst, const float* gsrc) {
    uint32_t d = (uint32_t)__cvta_generic_to_shared(smem_dst);
    asm volatile("cp.async.cg.shared.global [%0], [%1], 16;"
                 :: "r"(d), "l"(gsrc) : "memory");
}

// ---------------- front conv: obs (B,3,5,5) -> relu conv3x3 -> (B,288) ----
__global__ void conv_front(const float* __restrict__ obs,
                           const float* __restrict__ cw,
                           const float* __restrict__ cb) {
    int i = blockIdx.x * blockDim.x + threadIdx.x;
    if (i >= BSZ * 288) return;
    int b = i / 288, r = i % 288;
    int oc = r / 9, oi = (r % 9) / 3, oj = r % 3;
    const float* o = obs + b * 75;
    float s = cb[oc];
#pragma unroll
    for (int ci = 0; ci < 3; ci++)
#pragma unroll
        for (int ki = 0; ki < 3; ki++)
#pragma unroll
            for (int kj = 0; kj < 3; kj++)
                s += o[ci * 25 + (oi + ki) * 5 + (oj + kj)] *
                     cw[((oc * 3 + ci) * 3 + ki) * 3 + kj];
    g_v[i] = fmaxf(s, 0.f);
}

__global__ void copy_comm(const float* __restrict__ c) {
    int i = blockIdx.x * blockDim.x + threadIdx.x;
    if (i >= BSZ * 128) return;
    int b = i >> 7, j = i & 127;
    g_cat[b * 384 + 256 + j] = c[i];
}

// ---------------- TF32 tensor-core GEMM, cp.async 4-stage pipeline ----------
// C[M,N] (+)= act(A[M,K] @ B[K,N] + bias)
// BM=128, BN=64, BK=32, 256 threads (8 warps, 4x2 grid, 32x32 per warp).
// ACT: 0=none 1=relu 2=tanh 3=softplus 4=convsilu-on-x-half (cols<1024)
// Requires: M%128==0, N%64==0, K%32==0, 16B-aligned rows (all shapes comply)
#define AST 36          // A smem row stride (floats): bank = 4g+tg, conflict-free
#define BST 72          // B smem row stride (floats): bank = 8tg+g, conflict-free
#define A_FL (128 * AST)
#define B_FL (32 * BST)
#define STG_FL (A_FL + B_FL)
#define SMEM_BYTES (4 * STG_FL * 4)

template <int ACT, bool ACCUM, bool BIAS>
__global__ __launch_bounds__(256) void tgemm(
    const float* __restrict__ A, int lda,
    const float* __restrict__ B, int ldb,
    const float* __restrict__ bias,
    float* __restrict__ C, int ldc,
    int M, int N, int K,
    const float* __restrict__ cw1d, const float* __restrict__ cb1d) {
    extern __shared__ float sm[];

    int tid  = threadIdx.x;
    int lane = tid & 31;
    int warp = tid >> 5;
    int g  = lane >> 2;      // 0..7
    int tg = lane & 3;       // 0..3
    int wm = (warp & 3) * 32;
    int wn = (warp >> 2) * 32;
    int brow = blockIdx.y * 128;
    int bcol = blockIdx.x * 64;

    const int NT = K >> 5;

    // cp.async issue of one 32-deep K tile into a stage (always commits)
    auto issue = [&](int tile, int stage) {
        if (tile < NT) {
            float* Asb = sm + stage * STG_FL;
            float* Bsb = Asb + A_FL;
            int kt = tile << 5;
#pragma unroll
            for (int i = 0; i < 4; i++) {
                int idx = tid + i * 256;
                int r = idx >> 3, c = (idx & 7) << 2;
                cp16(Asb + r * AST + c, A + (size_t)(brow + r) * lda + kt + c);
            }
#pragma unroll
            for (int i = 0; i < 2; i++) {
                int idx = tid + i * 256;
                int kr = idx >> 4, c = (idx & 15) << 2;
                cp16(Bsb + kr * BST + c, B + (size_t)(kt + kr) * ldb + bcol + c);
            }
        }
        asm volatile("cp.async.commit_group;" ::: "memory");
    };

    float acc[2][4][4];
#pragma unroll
    for (int mt = 0; mt < 2; mt++)
#pragma unroll
        for (int nt = 0; nt < 4; nt++)
#pragma unroll
            for (int q = 0; q < 4; q++) acc[mt][nt][q] = 0.f;

    issue(0, 0);
    issue(1, 1);

    for (int t = 0; t < NT; t++) {
        issue(t + 2, (t + 2) & 3);
        asm volatile("cp.async.wait_group 2;" ::: "memory");
        __syncthreads();

        const float* Ab = sm + (t & 3) * STG_FL;
        const float* Bb = Ab + A_FL;
#pragma unroll
        for (int ks = 0; ks < 4; ks++) {
            int k0 = ks * 8;
            uint32_t af[2][4], bf[4][2];
#pragma unroll
            for (int mt = 0; mt < 2; mt++) {
                int mb = wm + mt * 16 + g;
                af[mt][0] = f2tf32(Ab[(size_t)mb * AST + k0 + tg]);
                af[mt][1] = f2tf32(Ab[(size_t)(mb + 8) * AST + k0 + tg]);
                af[mt][2] = f2tf32(Ab[(size_t)mb * AST + k0 + tg + 4]);
                af[mt][3] = f2tf32(Ab[(size_t)(mb + 8) * AST + k0 + tg + 4]);
            }
#pragma unroll
            for (int nt = 0; nt < 4; nt++) {
                int nb = wn + nt * 8 + g;
                bf[nt][0] = f2tf32(Bb[(size_t)(k0 + tg) * BST + nb]);
                bf[nt][1] = f2tf32(Bb[(size_t)(k0 + tg + 4) * BST + nb]);
            }
#pragma unroll
            for (int mt = 0; mt < 2; mt++)
#pragma unroll
                for (int nt = 0; nt < 4; nt++)
                    mma_tf32(acc[mt][nt], af[mt], bf[nt], acc[mt][nt]);
        }
        // single barrier per iter; stage distance 3 (mod 4) keeps writer/reader apart
    }

    // epilogue
#pragma unroll
    for (int nt = 0; nt < 4; nt++) {
        int col = bcol + wn + nt * 8 + 2 * tg;   // two consecutive cols
        float bv0 = 0.f, bv1 = 0.f;
        if (BIAS) { bv0 = bias[col]; bv1 = bias[col + 1]; }
        float cw0 = 0.f, cw1 = 0.f, cb0 = 0.f, cb1 = 0.f;
        bool xhalf = false;
        if (ACT == 4) {
            xhalf = col < 1024;  // 64-wide tiles never straddle 1024
            if (xhalf) {
                cw0 = cw1d[col * 4 + 3]; cw1 = cw1d[(col + 1) * 4 + 3];
                cb0 = cb1d[col];         cb1 = cb1d[col + 1];
            }
        }
#pragma unroll
        for (int mt = 0; mt < 2; mt++) {
#pragma unroll
            for (int half = 0; half < 2; half++) {
                int row = brow + wm + mt * 16 + g + half * 8;
                float v0 = acc[mt][nt][half * 2 + 0];
                float v1 = acc[mt][nt][half * 2 + 1];
                if (BIAS) { v0 += bv0; v1 += bv1; }
                if (ACT == 1) { v0 = fmaxf(v0, 0.f); v1 = fmaxf(v1, 0.f); }
                else if (ACT == 2) { v0 = tanhf(v0); v1 = tanhf(v1); }
                else if (ACT == 3) {
                    v0 = (v0 > 20.f) ? v0 : log1pf(expf(v0));
                    v1 = (v1 > 20.f) ? v1 : log1pf(expf(v1));
                } else if (ACT == 4) {
                    if (xhalf) {
                        v0 = v0 * cw0 + cb0; v0 = v0 / (1.f + expf(-v0));
                        v1 = v1 * cw1 + cb1; v1 = v1 / (1.f + expf(-v1));
                    }
                }
                float* cp = C + (size_t)row * ldc + col;
                if (ACCUM) {
                    float2 prev = *(const float2*)cp;
                    v0 += prev.x; v1 += prev.y;
                }
                *(float2*)cp = make_float2(v0, v1);
            }
        }
    }
}

// ---------------- rmsnorm: one warp per 512-row -----------------------------
__global__ void rmsnorm_k(const float* __restrict__ x, const float* __restrict__ w,
                          float* __restrict__ out) {
    int warp = (blockIdx.x * blockDim.x + threadIdx.x) >> 5;
    int lane = threadIdx.x & 31;
    if (warp >= BSZ) return;
    const float4* xr = (const float4*)(x + (size_t)warp * 512);
    float4 v[4];
    float ss = 0.f;
#pragma unroll
    for (int i = 0; i < 4; i++) {
        v[i] = xr[lane + i * 32];
        ss += v[i].x * v[i].x + v[i].y * v[i].y + v[i].z * v[i].z + v[i].w * v[i].w;
    }
#pragma unroll
    for (int o = 16; o > 0; o >>= 1) ss += __shfl_xor_sync(0xffffffffu, ss, o);
    float sc = rsqrtf(ss * (1.f / 512.f) + 1e-5f);
    float4* orow = (float4*)(out + (size_t)warp * 512);
    const float4* wr = (const float4*)w;
#pragma unroll
    for (int i = 0; i < 4; i++) {
        float4 wv = wr[lane + i * 32];
        float4 r;
        r.x = v[i].x * sc * wv.x; r.y = v[i].y * sc * wv.y;
        r.z = v[i].z * sc * wv.z; r.w = v[i].w * sc * wv.w;
        orow[lane + i * 32] = r;
    }
}

// ---------------- fused y = (dt*<B,C> + D)*x*silu(z) ------------------------
__global__ void fused_y(const float* __restrict__ Dp) {
    int b = blockIdx.x;
    __shared__ float sh[16];
    __shared__ float bc_sh;
    int t = threadIdx.x;
    if (t < 16) sh[t] = g_xdbl[b * 64 + 32 + t] * g_xdbl[b * 64 + 48 + t];
    __syncthreads();
    if (t == 0) {
        float s = 0.f;
#pragma unroll
        for (int i = 0; i < 16; i++) s += sh[i];
        bc_sh = s;
    }
    __syncthreads();
    float bc = bc_sh;
    for (int d = t; d < 1024; d += 256) {
        float x  = g_xz[(size_t)b * 2048 + d];
        float z  = g_xz[(size_t)b * 2048 + 1024 + d];
        float dt = g_dt[(size_t)b * 1024 + d];
        float y  = (dt * bc + Dp[d]) * x;
        float sz = z / (1.f + expf(-z));
        g_y[(size_t)b * 1024 + d] = y * sz;
    }
}

// ---------------- action + value heads: one warp per row --------------------
__global__ void heads_k(const float* __restrict__ aw, const float* __restrict__ ab,
                        const float* __restrict__ vw, const float* __restrict__ vb,
                        float* __restrict__ out) {
    int warp = (blockIdx.x * blockDim.x + threadIdx.x) >> 5;
    int lane = threadIdx.x & 31;
    if (warp >= BSZ) return;
    const float* u = g_u + (size_t)warp * 512;
    float s0 = 0, s1 = 0, s2 = 0, s3 = 0, s4 = 0;
    for (int d = lane; d < 512; d += 32) {
        float uv = u[d];
        float4 w4 = *(const float4*)(aw + d * 4);
        s0 += uv * w4.x; s1 += uv * w4.y; s2 += uv * w4.z; s3 += uv * w4.w;
        s4 += uv * vw[d];
    }
#pragma unroll
    for (int o = 16; o > 0; o >>= 1) {
        s0 += __shfl_xor_sync(0xffffffffu, s0, o);
        s1 += __shfl_xor_sync(0xffffffffu, s1, o);
        s2 += __shfl_xor_sync(0xffffffffu, s2, o);
        s3 += __shfl_xor_sync(0xffffffffu, s3, o);
        s4 += __shfl_xor_sync(0xffffffffu, s4, o);
    }
    if (lane == 0) {
        out[warp * 4 + 0] = s0 + ab[0];
        out[warp * 4 + 1] = s1 + ab[1];
        out[warp * 4 + 2] = s2 + ab[2];
        out[warp * 4 + 3] = s3 + ab[3];
        out[(size_t)BSZ * 4 + (size_t)BSZ * 128 + warp] = s4 + vb[0];
    }
}

// ---------------- launch --------------------------------------------------
template <int ACT, bool ACCUM, bool BIAS>
static void launch_tgemm(const float* A, int lda, const float* B, int ldb,
                         const float* bias, float* C, int ldc,
                         int M, int N, int K,
                         const float* cw1d, const float* cb1d) {
    cudaFuncSetAttribute(tgemm<ACT, ACCUM, BIAS>,
                         cudaFuncAttributeMaxDynamicSharedMemorySize, SMEM_BYTES);
    tgemm<ACT, ACCUM, BIAS><<<dim3(N / 64, M / 128), 256, SMEM_BYTES>>>(
        A, lda, B, ldb, bias, C, ldc, M, N, K, cw1d, cb1d);
}

extern "C" void kernel_launch(void* const* d_in, const int* in_sizes, int n_in,
                              void* d_out, int out_size) {
    const float* obs     = (const float*)d_in[0];
    const float* comm_in = (const float*)d_in[1];
    const float* conv_w  = (const float*)d_in[2];
    const float* conv_b  = (const float*)d_in[3];
    const float* enc_w   = (const float*)d_in[4];
    const float* enc_b   = (const float*)d_in[5];
    const float* proj_w  = (const float*)d_in[6];
    const float* proj_b  = (const float*)d_in[7];
    const float* norm_w  = (const float*)d_in[8];
    const float* in_proj_w = (const float*)d_in[9];
    const float* conv1d_w  = (const float*)d_in[10];
    const float* conv1d_b  = (const float*)d_in[11];
    const float* x_proj_w  = (const float*)d_in[12];
    const float* dt_proj_w = (const float*)d_in[13];
    const float* dt_proj_b = (const float*)d_in[14];
    // d_in[15] = A_log: dead (h0 == 0 makes dA irrelevant at L=1)
    const float* D_param    = (const float*)d_in[16];
    const float* out_proj_w = (const float*)d_in[17];
    const float* final_norm = (const float*)d_in[18];
    const float* act_w  = (const float*)d_in[19];
    const float* act_b  = (const float*)d_in[20];
    const float* comm_w = (const float*)d_in[21];
    const float* comm_b = (const float*)d_in[22];
    const float* val_w  = (const float*)d_in[23];
    const float* val_b  = (const float*)d_in[24];
    float* out = (float*)d_out;

    float* gv    = nullptr; cudaGetSymbolAddress((void**)&gv, g_v);
    float* gcat  = nullptr; cudaGetSymbolAddress((void**)&gcat, g_cat);
    float* gh    = nullptr; cudaGetSymbolAddress((void**)&gh, g_h);
    float* gu    = nullptr; cudaGetSymbolAddress((void**)&gu, g_u);
    float* gxz   = nullptr; cudaGetSymbolAddress((void**)&gxz, g_xz);
    float* gxdbl = nullptr; cudaGetSymbolAddress((void**)&gxdbl, g_xdbl);
    float* gdt   = nullptr; cudaGetSymbolAddress((void**)&gdt, g_dt);
    float* gy    = nullptr; cudaGetSymbolAddress((void**)&gy, g_y);

    const int M = BSZ;

    // front
    conv_front<<<(BSZ * 288 + 255) / 256, 256>>>(obs, conv_w, conv_b);
    launch_tgemm<1, false, true>(gv, 288, enc_w, 256, enc_b, gcat, 384,
                                 M, 256, 288, nullptr, nullptr);
    copy_comm<<<(BSZ * 128 + 255) / 256, 256>>>(comm_in);
    launch_tgemm<1, false, true>(gcat, 384, proj_w, 512, proj_b, gh, 512,
                                 M, 512, 384, nullptr, nullptr);

    // two mamba layers (L=1 closed form)
    for (int l = 0; l < 2; l++) {
        rmsnorm_k<<<BSZ / 8, 256>>>(gh, norm_w + l * 512, gu);
        // in_proj with fused depthwise-conv-tap + silu on x-half columns
        launch_tgemm<4, false, false>(gu, 512, in_proj_w + (size_t)l * 512 * 2048,
                                      2048, nullptr, gxz, 2048, M, 2048, 512,
                                      conv1d_w + (size_t)l * 1024 * 4,
                                      conv1d_b + (size_t)l * 1024);
        launch_tgemm<0, false, false>(gxz, 2048, x_proj_w + (size_t)l * 1024 * 64,
                                      64, nullptr, gxdbl, 64, M, 64, 1024,
                                      nullptr, nullptr);
        launch_tgemm<3, false, true>(gxdbl, 64, dt_proj_w + (size_t)l * 32 * 1024,
                                     1024, dt_proj_b + (size_t)l * 1024,
                                     gdt, 1024, M, 1024, 32, nullptr, nullptr);
        fused_y<<<BSZ, 256>>>(D_param + (size_t)l * 1024);
        launch_tgemm<0, true, false>(gy, 1024, out_proj_w + (size_t)l * 1024 * 512,
                                     512, nullptr, gh, 512, M, 512, 1024,
                                     nullptr, nullptr);
    }

    // final norm + heads
    rmsnorm_k<<<BSZ / 8, 256>>>(gh, final_norm, gu);
    launch_tgemm<2, false, true>(gu, 512, comm_w, 128, comm_b,
                                 out + (size_t)BSZ * 4, 128, M, 128, 512,
                                 nullptr, nullptr);
    heads_k<<<BSZ / 8, 256>>>(act_w, act_b, val_w, val_b, out);
}

// round 16
// speedup vs baseline: 2.7204x; 1.0565x over previous
#include <cuda_runtime.h>
#include <math.h>
#include <stdint.h>

#define BSZ 8192

// ---------------- scratch (static device globals; no allocs allowed) -------
__device__ float g_v[BSZ * 288];      // conv front output (tf32-rounded)
__device__ float g_cat[BSZ * 384];    // [emb | comm] (tf32-rounded)
__device__ float g_h[BSZ * 512];      // residual stream (raw fp32)
__device__ float g_u[BSZ * 512];      // final rmsnorm raw (heads_k)
__device__ float g_ur[BSZ * 512];     // rmsnorm tf32-rounded (GEMM A)
__device__ float g_xz[BSZ * 2048];    // in_proj output raw (silu(conv(x)) | z)
__device__ float g_xdbl[BSZ * 64];    // x_proj output raw
__device__ float g_dt[BSZ * 1024];    // softplus(dt) raw
__device__ float g_y[BSZ * 1024];     // gated y (tf32-rounded)

// tf32-preconverted weights
__device__ float wt_enc[288 * 256];
__device__ float wt_proj[384 * 512];
__device__ float wt_in[2 * 512 * 2048];
__device__ float wt_x[2 * 1024 * 64];
__device__ float wt_dt[2 * 32 * 1024];
__device__ float wt_out[2 * 1024 * 512];
__device__ float wt_comm[512 * 128];

// ---------------- helpers ---------------------------------------------------
__device__ __forceinline__ uint32_t f2tf32(float f) {
    uint32_t u;
    asm("cvt.rna.tf32.f32 %0, %1;" : "=r"(u) : "f"(f));
    return u;
}
__device__ __forceinline__ float tf32r(float f) {
    return __uint_as_float(f2tf32(f));
}

__device__ __forceinline__ void mma_tf32(float* d, const uint32_t* a,
                                         const uint32_t* b, const float* c) {
    asm volatile(
        "mma.sync.aligned.m16n8k8.row.col.f32.tf32.tf32.f32 "
        "{%0,%1,%2,%3}, {%4,%5,%6,%7}, {%8,%9}, {%10,%11,%12,%13};"
        : "=f"(d[0]), "=f"(d[1]), "=f"(d[2]), "=f"(d[3])
        : "r"(a[0]), "r"(a[1]), "r"(a[2]), "r"(a[3]),
          "r"(b[0]), "r"(b[1]),
          "f"(c[0]), "f"(c[1]), "f"(c[2]), "f"(c[3]));
}

__device__ __forceinline__ void cp16(float* smem_dst, const float* gsrc) {
    uint32_t d = (uint32_t)__cvta_generic_to_shared(smem_dst);
    asm volatile("cp.async.cg.shared.global [%0], [%1], 16;"
                 :: "r"(d), "l"(gsrc) : "memory");
}

// ---------------- weight tf32 preconvert ------------------------------------
__global__ void cvtw(const float* __restrict__ s, float* __restrict__ d, int n) {
    int i = blockIdx.x * blockDim.x + threadIdx.x;
    if (i < n) d[i] = tf32r(s[i]);
}

// ---------------- front conv: obs (B,3,5,5) -> relu conv3x3 -> (B,288) ----
__global__ void conv_front(const float* __restrict__ obs,
                           const float* __restrict__ cw,
                           const float* __restrict__ cb) {
    int i = blockIdx.x * blockDim.x + threadIdx.x;
    if (i >= BSZ * 288) return;
    int b = i / 288, r = i % 288;
    int oc = r / 9, oi = (r % 9) / 3, oj = r % 3;
    const float* o = obs + b * 75;
    float s = cb[oc];
#pragma unroll
    for (int ci = 0; ci < 3; ci++)
#pragma unroll
        for (int ki = 0; ki < 3; ki++)
#pragma unroll
            for (int kj = 0; kj < 3; kj++)
                s += o[ci * 25 + (oi + ki) * 5 + (oj + kj)] *
                     cw[((oc * 3 + ci) * 3 + ki) * 3 + kj];
    g_v[i] = tf32r(fmaxf(s, 0.f));
}

__global__ void copy_comm(const float* __restrict__ c) {
    int i = blockIdx.x * blockDim.x + threadIdx.x;
    if (i >= BSZ * 128) return;
    int b = i >> 7, j = i & 127;
    g_cat[b * 384 + 256 + j] = tf32r(c[i]);
}

// ---------------- TF32 tensor-core GEMM, cp.async 4-stage pipeline ----------
// C[M,N] (+)= act(A[M,K] @ B[K,N] + bias)
// BM=128, BN=64, BK=32, 256 threads (8 warps, 4x2 grid, 32x32 per warp).
// ACT: 0=none 1=relu 2=tanh 3=softplus 4=convsilu-on-x-half (cols<1024)
// CVTA: convert A fragments (A not pre-rounded). B must ALWAYS be pre-rounded.
// ROUNDC: tf32-round stored C (output feeds a GEMM A-side with no CVTA)
#define AST 36          // A smem row stride (floats): bank = 4g+tg, conflict-free
#define BST 72          // B smem row stride (floats): bank = 8tg+g, conflict-free
#define A_FL (128 * AST)
#define B_FL (32 * BST)
#define STG_FL (A_FL + B_FL)
#define SMEM_BYTES (4 * STG_FL * 4)

template <int ACT, bool ACCUM, bool BIAS, bool CVTA, bool ROUNDC>
__global__ __launch_bounds__(256) void tgemm(
    const float* __restrict__ A, int lda,
    const float* __restrict__ B, int ldb,
    const float* __restrict__ bias,
    float* __restrict__ C, int ldc,
    int M, int N, int K,
    const float* __restrict__ cw1d, const float* __restrict__ cb1d) {
    extern __shared__ float sm[];

    int tid  = threadIdx.x;
    int lane = tid & 31;
    int warp = tid >> 5;
    int g  = lane >> 2;      // 0..7
    int tg = lane & 3;       // 0..3
    int wm = (warp & 3) * 32;
    int wn = (warp >> 2) * 32;
    int brow = blockIdx.y * 128;
    int bcol = blockIdx.x * 64;

    const int NT = K >> 5;

    auto issue = [&](int tile, int stage) {
        if (tile < NT) {
            float* Asb = sm + stage * STG_FL;
            float* Bsb = Asb + A_FL;
            int kt = tile << 5;
#pragma unroll
            for (int i = 0; i < 4; i++) {
                int idx = tid + i * 256;
                int r = idx >> 3, c = (idx & 7) << 2;
                cp16(Asb + r * AST + c, A + (size_t)(brow + r) * lda + kt + c);
            }
#pragma unroll
            for (int i = 0; i < 2; i++) {
                int idx = tid + i * 256;
                int kr = idx >> 4, c = (idx & 15) << 2;
                cp16(Bsb + kr * BST + c, B + (size_t)(kt + kr) * ldb + bcol + c);
            }
        }
        asm volatile("cp.async.commit_group;" ::: "memory");
    };

    float acc[2][4][4];
#pragma unroll
    for (int mt = 0; mt < 2; mt++)
#pragma unroll
        for (int nt = 0; nt < 4; nt++)
#pragma unroll
            for (int q = 0; q < 4; q++) acc[mt][nt][q] = 0.f;

    issue(0, 0);
    issue(1, 1);

    for (int t = 0; t < NT; t++) {
        issue(t + 2, (t + 2) & 3);
        asm volatile("cp.async.wait_group 2;" ::: "memory");
        __syncthreads();

        const uint32_t* Ab = (const uint32_t*)(sm + (t & 3) * STG_FL);
        const uint32_t* Bb = Ab + A_FL;
#pragma unroll
        for (int ks = 0; ks < 4; ks++) {
            int k0 = ks * 8;
            uint32_t af[2][4], bf[4][2];
#pragma unroll
            for (int mt = 0; mt < 2; mt++) {
                int mb = (wm + mt * 16 + g) * AST;
                if (CVTA) {
                    af[mt][0] = f2tf32(__uint_as_float(Ab[mb + k0 + tg]));
                    af[mt][1] = f2tf32(__uint_as_float(Ab[mb + 8 * AST + k0 + tg]));
                    af[mt][2] = f2tf32(__uint_as_float(Ab[mb + k0 + tg + 4]));
                    af[mt][3] = f2tf32(__uint_as_float(Ab[mb + 8 * AST + k0 + tg + 4]));
                } else {
                    af[mt][0] = Ab[mb + k0 + tg];
                    af[mt][1] = Ab[mb + 8 * AST + k0 + tg];
                    af[mt][2] = Ab[mb + k0 + tg + 4];
                    af[mt][3] = Ab[mb + 8 * AST + k0 + tg + 4];
                }
            }
#pragma unroll
            for (int nt = 0; nt < 4; nt++) {
                int nb = wn + nt * 8 + g;
                bf[nt][0] = Bb[(k0 + tg) * BST + nb];
                bf[nt][1] = Bb[(k0 + tg + 4) * BST + nb];
            }
#pragma unroll
            for (int mt = 0; mt < 2; mt++)
#pragma unroll
                for (int nt = 0; nt < 4; nt++)
                    mma_tf32(acc[mt][nt], af[mt], bf[nt], acc[mt][nt]);
        }
    }

    // epilogue
#pragma unroll
    for (int nt = 0; nt < 4; nt++) {
        int col = bcol + wn + nt * 8 + 2 * tg;
        float bv0 = 0.f, bv1 = 0.f;
        if (BIAS) { bv0 = bias[col]; bv1 = bias[col + 1]; }
        float cw0 = 0.f, cw1 = 0.f, cb0 = 0.f, cb1 = 0.f;
        bool xhalf = false;
        if (ACT == 4) {
            xhalf = col < 1024;
            if (xhalf) {
                cw0 = cw1d[col * 4 + 3]; cw1 = cw1d[(col + 1) * 4 + 3];
                cb0 = cb1d[col];         cb1 = cb1d[col + 1];
            }
        }
#pragma unroll
        for (int mt = 0; mt < 2; mt++) {
#pragma unroll
            for (int half = 0; half < 2; half++) {
                int row = brow + wm + mt * 16 + g + half * 8;
                float v0 = acc[mt][nt][half * 2 + 0];
                float v1 = acc[mt][nt][half * 2 + 1];
                if (BIAS) { v0 += bv0; v1 += bv1; }
                if (ACT == 1) { v0 = fmaxf(v0, 0.f); v1 = fmaxf(v1, 0.f); }
                else if (ACT == 2) { v0 = tanhf(v0); v1 = tanhf(v1); }
                else if (ACT == 3) {
                    v0 = (v0 > 20.f) ? v0 : log1pf(expf(v0));
                    v1 = (v1 > 20.f) ? v1 : log1pf(expf(v1));
                } else if (ACT == 4) {
                    if (xhalf) {
                        v0 = v0 * cw0 + cb0; v0 = v0 / (1.f + expf(-v0));
                        v1 = v1 * cw1 + cb1; v1 = v1 / (1.f + expf(-v1));
                    }
                }
                float* cp = C + (size_t)row * ldc + col;
                if (ACCUM) {
                    float2 prev = *(const float2*)cp;
                    v0 += prev.x; v1 += prev.y;
                }
                if (ROUNDC) { v0 = tf32r(v0); v1 = tf32r(v1); }
                *(float2*)cp = make_float2(v0, v1);
            }
        }
    }
}

// ---------------- rmsnorm: one warp per 512-row -----------------------------
// outr: tf32-rounded (GEMM A side); outraw: optional raw copy (heads)
__global__ void rmsnorm_k(const float* __restrict__ x, const float* __restrict__ w,
                          float* __restrict__ outr, float* __restrict__ outraw) {
    int warp = (blockIdx.x * blockDim.x + threadIdx.x) >> 5;
    int lane = threadIdx.x & 31;
    if (warp >= BSZ) return;
    const float4* xr = (const float4*)(x + (size_t)warp * 512);
    float4 v[4];
    float ss = 0.f;
#pragma unroll
    for (int i = 0; i < 4; i++) {
        v[i] = xr[lane + i * 32];
        ss += v[i].x * v[i].x + v[i].y * v[i].y + v[i].z * v[i].z + v[i].w * v[i].w;
    }
#pragma unroll
    for (int o = 16; o > 0; o >>= 1) ss += __shfl_xor_sync(0xffffffffu, ss, o);
    float sc = rsqrtf(ss * (1.f / 512.f) + 1e-5f);
    float4* orow = (float4*)(outr + (size_t)warp * 512);
    float4* orraw = outraw ? (float4*)(outraw + (size_t)warp * 512) : nullptr;
    const float4* wr = (const float4*)w;
#pragma unroll
    for (int i = 0; i < 4; i++) {
        float4 wv = wr[lane + i * 32];
        float4 r;
        r.x = v[i].x * sc * wv.x; r.y = v[i].y * sc * wv.y;
        r.z = v[i].z * sc * wv.z; r.w = v[i].w * sc * wv.w;
        if (orraw) orraw[lane + i * 32] = r;
        float4 rr;
        rr.x = tf32r(r.x); rr.y = tf32r(r.y);
        rr.z = tf32r(r.z); rr.w = tf32r(r.w);
        orow[lane + i * 32] = rr;
    }
}

// ---------------- fused y = (dt*<B,C> + D)*x*silu(z), tf32-rounded ----------
__global__ void fused_y(const float* __restrict__ Dp) {
    int b = blockIdx.x;
    __shared__ float sh[16];
    __shared__ float bc_sh;
    int t = threadIdx.x;
    if (t < 16) sh[t] = g_xdbl[b * 64 + 32 + t] * g_xdbl[b * 64 + 48 + t];
    __syncthreads();
    if (t == 0) {
        float s = 0.f;
#pragma unroll
        for (int i = 0; i < 16; i++) s += sh[i];
        bc_sh = s;
    }
    __syncthreads();
    float bc = bc_sh;
    for (int d = t; d < 1024; d += 256) {
        float x  = g_xz[(size_t)b * 2048 + d];
        float z  = g_xz[(size_t)b * 2048 + 1024 + d];
        float dt = g_dt[(size_t)b * 1024 + d];
        float y  = (dt * bc + Dp[d]) * x;
        float sz = z / (1.f + expf(-z));
        g_y[(size_t)b * 1024 + d] = tf32r(y * sz);
    }
}

// ---------------- action + value heads: one warp per row --------------------
__global__ void heads_k(const float* __restrict__ aw, const float* __restrict__ ab,
                        const float* __restrict__ vw, const float* __restrict__ vb,
                        float* __restrict__ out) {
    int warp = (blockIdx.x * blockDim.x + threadIdx.x) >> 5;
    int lane = threadIdx.x & 31;
    if (warp >= BSZ) return;
    const float* u = g_u + (size_t)warp * 512;
    float s0 = 0, s1 = 0, s2 = 0, s3 = 0, s4 = 0;
    for (int d = lane; d < 512; d += 32) {
        float uv = u[d];
        float4 w4 = *(const float4*)(aw + d * 4);
        s0 += uv * w4.x; s1 += uv * w4.y; s2 += uv * w4.z; s3 += uv * w4.w;
        s4 += uv * vw[d];
    }
#pragma unroll
    for (int o = 16; o > 0; o >>= 1) {
        s0 += __shfl_xor_sync(0xffffffffu, s0, o);
        s1 += __shfl_xor_sync(0xffffffffu, s1, o);
        s2 += __shfl_xor_sync(0xffffffffu, s2, o);
        s3 += __shfl_xor_sync(0xffffffffu, s3, o);
        s4 += __shfl_xor_sync(0xffffffffu, s4, o);
    }
    if (lane == 0) {
        out[warp * 4 + 0] = s0 + ab[0];
        out[warp * 4 + 1] = s1 + ab[1];
        out[warp * 4 + 2] = s2 + ab[2];
        out[warp * 4 + 3] = s3 + ab[3];
        out[(size_t)BSZ * 4 + (size_t)BSZ * 128 + warp] = s4 + vb[0];
    }
}

// ---------------- launch --------------------------------------------------
template <int ACT, bool ACCUM, bool BIAS, bool CVTA, bool ROUNDC>
static void launch_tgemm(const float* A, int lda, const float* B, int ldb,
                         const float* bias, float* C, int ldc,
                         int M, int N, int K,
                         const float* cw1d, const float* cb1d) {
    cudaFuncSetAttribute(tgemm<ACT, ACCUM, BIAS, CVTA, ROUNDC>,
                         cudaFuncAttributeMaxDynamicSharedMemorySize, SMEM_BYTES);
    tgemm<ACT, ACCUM, BIAS, CVTA, ROUNDC><<<dim3(N / 64, M / 128), 256, SMEM_BYTES>>>(
        A, lda, B, ldb, bias, C, ldc, M, N, K, cw1d, cb1d);
}

static void launch_cvtw(const float* src, float* dst, int n) {
    cvtw<<<(n + 255) / 256, 256>>>(src, dst, n);
}

extern "C" void kernel_launch(void* const* d_in, const int* in_sizes, int n_in,
                              void* d_out, int out_size) {
    const float* obs     = (const float*)d_in[0];
    const float* comm_in = (const float*)d_in[1];
    const float* conv_w  = (const float*)d_in[2];
    const float* conv_b  = (const float*)d_in[3];
    const float* enc_w   = (const float*)d_in[4];
    const float* enc_b   = (const float*)d_in[5];
    const float* proj_w  = (const float*)d_in[6];
    const float* proj_b  = (const float*)d_in[7];
    const float* norm_w  = (const float*)d_in[8];
    const float* in_proj_w = (const float*)d_in[9];
    const float* conv1d_w  = (const float*)d_in[10];
    const float* conv1d_b  = (const float*)d_in[11];
    const float* x_proj_w  = (const float*)d_in[12];
    const float* dt_proj_w = (const float*)d_in[13];
    const float* dt_proj_b = (const float*)d_in[14];
    // d_in[15] = A_log: dead (h0 == 0 makes dA irrelevant at L=1)
    const float* D_param    = (const float*)d_in[16];
    const float* out_proj_w = (const float*)d_in[17];
    const float* final_norm = (const float*)d_in[18];
    const float* act_w  = (const float*)d_in[19];
    const float* act_b  = (const float*)d_in[20];
    const float* comm_w = (const float*)d_in[21];
    const float* comm_b = (const float*)d_in[22];
    const float* val_w  = (const float*)d_in[23];
    const float* val_b  = (const float*)d_in[24];
    float* out = (float*)d_out;

    float* gv    = nullptr; cudaGetSymbolAddress((void**)&gv, g_v);
    float* gcat  = nullptr; cudaGetSymbolAddress((void**)&gcat, g_cat);
    float* gh    = nullptr; cudaGetSymbolAddress((void**)&gh, g_h);
    float* gu    = nullptr; cudaGetSymbolAddress((void**)&gu, g_u);
    float* gur   = nullptr; cudaGetSymbolAddress((void**)&gur, g_ur);
    float* gxz   = nullptr; cudaGetSymbolAddress((void**)&gxz, g_xz);
    float* gxdbl = nullptr; cudaGetSymbolAddress((void**)&gxdbl, g_xdbl);
    float* gdt   = nullptr; cudaGetSymbolAddress((void**)&gdt, g_dt);
    float* gy    = nullptr; cudaGetSymbolAddress((void**)&gy, g_y);
    float* wenc  = nullptr; cudaGetSymbolAddress((void**)&wenc, wt_enc);
    float* wproj = nullptr; cudaGetSymbolAddress((void**)&wproj, wt_proj);
    float* win   = nullptr; cudaGetSymbolAddress((void**)&win, wt_in);
    float* wx    = nullptr; cudaGetSymbolAddress((void**)&wx, wt_x);
    float* wdt   = nullptr; cudaGetSymbolAddress((void**)&wdt, wt_dt);
    float* wout  = nullptr; cudaGetSymbolAddress((void**)&wout, wt_out);
    float* wcomm = nullptr; cudaGetSymbolAddress((void**)&wcomm, wt_comm);

    const int M = BSZ;

    // per-launch tf32 preconversion of all GEMM B-matrices
    launch_cvtw(enc_w, wenc, 288 * 256);
    launch_cvtw(proj_w, wproj, 384 * 512);
    launch_cvtw(in_proj_w, win, 2 * 512 * 2048);
    launch_cvtw(x_proj_w, wx, 2 * 1024 * 64);
    launch_cvtw(dt_proj_w, wdt, 2 * 32 * 1024);
    launch_cvtw(out_proj_w, wout, 2 * 1024 * 512);
    launch_cvtw(comm_w, wcomm, 512 * 128);

    // front
    conv_front<<<(BSZ * 288 + 255) / 256, 256>>>(obs, conv_w, conv_b);
    launch_tgemm<1, false, true, false, true>(gv, 288, wenc, 256, enc_b,
                                              gcat, 384, M, 256, 288,
                                              nullptr, nullptr);
    copy_comm<<<(BSZ * 128 + 255) / 256, 256>>>(comm_in);
    launch_tgemm<1, false, true, false, false>(gcat, 384, wproj, 512, proj_b,
                                               gh, 512, M, 512, 384,
                                               nullptr, nullptr);

    // two mamba layers (L=1 closed form)
    for (int l = 0; l < 2; l++) {
        rmsnorm_k<<<BSZ / 8, 256>>>(gh, norm_w + l * 512, gur, nullptr);
        launch_tgemm<4, false, false, false, false>(
            gur, 512, win + (size_t)l * 512 * 2048, 2048, nullptr,
            gxz, 2048, M, 2048, 512,
            conv1d_w + (size_t)l * 1024 * 4, conv1d_b + (size_t)l * 1024);
        launch_tgemm<0, false, false, true, false>(
            gxz, 2048, wx + (size_t)l * 1024 * 64, 64, nullptr,
            gxdbl, 64, M, 64, 1024, nullptr, nullptr);
        launch_tgemm<3, false, true, true, false>(
            gxdbl, 64, wdt + (size_t)l * 32 * 1024, 1024,
            dt_proj_b + (size_t)l * 1024, gdt, 1024, M, 1024, 32,
            nullptr, nullptr);
        fused_y<<<BSZ, 256>>>(D_param + (size_t)l * 1024);
        launch_tgemm<0, true, false, false, false>(
            gy, 1024, wout + (size_t)l * 1024 * 512, 512, nullptr,
            gh, 512, M, 512, 1024, nullptr, nullptr);
    }

    // final norm + heads
    rmsnorm_k<<<BSZ / 8, 256>>>(gh, final_norm, gur, gu);
    launch_tgemm<2, false, true, false, false>(gur, 512, wcomm, 128, comm_b,
                                               out + (size_t)BSZ * 4, 128,
                                               M, 128, 512, nullptr, nullptr);
    heads_k<<<BSZ / 8, 256>>>(act_w, act_b, val_w, val_b, out);
}